// round 8
// baseline (speedup 1.0000x reference)
#include <cuda_runtime.h>
#include <math.h>

// out[m,n] = rope(a,m) . rope(b,n) depends only on (m-n):
//   out[m,n] = sum_j P_j*cos((m-n)*f_j) + Q_j*sin((m-n)*f_j)
// Build g(d) once (2c-1 values), then Toeplitz broadcast-fill.

__device__ float g_table[32768];
__device__ unsigned int tile_ctr;     // work-stealing cursor for fill

#define FILL_GRID 1216                // 8 blocks x 152 SMs (GB300)

// ---------------- Kernel A: generator table ----------------
// One warp produces BOTH g(+d) and g(-d) from one sincos pass:
//   g(+d) = sum P*cos + Q*sin ,  g(-d) = sum P*cos - Q*sin
__global__ void __launch_bounds__(512) compute_g_kernel(
        const float* __restrict__ a,
        const float* __restrict__ b,
        int c) {
    __shared__ float  Psh[64];
    __shared__ float  Qsh[64];
    __shared__ double Fsh[64];

    const int t = threadIdx.x;
    if (blockIdx.x == 0 && t == 0)
        tile_ctr = FILL_GRID;         // reset cursor for the fill kernel
    if (t < 64) {
        float a1 = a[t], a2 = a[t + 64];
        float b1 = b[t], b2 = b[t + 64];
        Psh[t] = a1 * b1 + a2 * b2;
        Qsh[t] = a1 * b2 - a2 * b1;
        // inv_freq[j] = 10000^(-j/64) = exp(-j * ln(10000)/64)
        Fsh[t] = exp(-(double)t * 0.14391156831212785);
    }
    __syncthreads();

    const int lane = t & 31;
    const int i    = blockIdx.x * (blockDim.x >> 5) + (t >> 5);  // d = i
    if (i >= c) return;

    const double d      = (double)i;
    const double inv2pi = 0.15915494309189535;
    const double twopi  = 6.283185307179586;

    float accP = 0.0f, accQ = 0.0f;
#pragma unroll
    for (int jj = 0; jj < 2; jj++) {
        int j = lane + jj * 32;
        double ang = d * Fsh[j];
        double k   = rint(ang * inv2pi);       // double range reduction
        float  r   = (float)(ang - k * twopi); // safe for fast-math sincosf
        float s, co;
        sincosf(r, &s, &co);
        accP += Psh[j] * co;
        accQ += Qsh[j] * s;
    }
#pragma unroll
    for (int o = 16; o; o >>= 1) {
        accP += __shfl_xor_sync(0xFFFFFFFFu, accP, o);
        accQ += __shfl_xor_sync(0xFFFFFFFFu, accQ, o);
    }

    if (lane == 0) {
        g_table[(c - 1) + i] = accP + accQ;   // g(+d)
        g_table[(c - 1) - i] = accP - accQ;   // g(-d)
    }
}

// ---------------- Kernel B: persistent Toeplitz fill ----------------
// Tile: 32 x 1024 (256 threads, one float4-column per thread). Reversed
// slice rsm0[k] = g[hi-k] stored in 4 shift-copies so every (row, col4)
// access is an aligned, conflict-free LDS.128. Tiles are handed out by a
// global atomic cursor for near-perfect SM load balance.
#define TROWS   32
#define TCOLS   1024
#define KLEN    (TCOLS + TROWS - 1)     // 1055 used indices
#define SSTRIDE 1060                    // float stride per copy (16B-mult)

__global__ void __launch_bounds__(256, 8) fill_kernel(float4* __restrict__ out, int c) {
    __shared__ float rsm[4 * SSTRIDE];
    __shared__ unsigned int s_tile;

    const int t      = threadIdx.x;
    const int ntx    = c / TCOLS;                  // col-tiles per row
    const int nTiles = ntx * (c / TROWS);
    const int gmax   = 2 * c - 2;
    const int cq     = c >> 2;

    unsigned int tile = blockIdx.x;                // first tile: static
    for (;;) {
        if (tile >= (unsigned)nTiles) return;

        const int by = (int)tile / ntx;
        const int bx = (int)tile - by * ntx;
        const int m0 = by * TROWS;
        const int n0 = bx * TCOLS;
        const int base0 = (c - 1) + m0 - n0;
        const int hi    = base0 + TROWS - 1;

        // Stage 4 shifted reversed copies: copy_s[k] = g[hi - k - s]
#pragma unroll
        for (int s = 0; s < 4; s++) {
            for (int k = t; k < KLEN; k += 256) {
                int gi = hi - k - s;
                rsm[s * SSTRIDE + k] = (gi >= 0 && gi <= gmax) ? g_table[gi] : 0.0f;
            }
        }
        __syncthreads();

        float4* orow = out + (size_t)m0 * (size_t)cq + (n0 >> 2) + t;
        // row r, col 4t+e -> g[base0 + r - 4t - e] = rsm0[x + 4t + e],
        // x = TROWS-1-r; with s = x&3: aligned float4 at copy_s[(x-s) + 4t].
#pragma unroll
        for (int r = 0; r < TROWS; r++) {
            const int x = TROWS - 1 - r;
            const int s = x & 3;                   // compile-time per r
            const float4* src =
                (const float4*)(rsm + s * SSTRIDE + (x - s)) + t;
            orow[(size_t)r * (size_t)cq] = *src;
        }
        __syncthreads();                           // reads done before restage

        if (t == 0) s_tile = atomicAdd(&tile_ctr, 1u);
        __syncthreads();
        tile = s_tile;
    }
}

extern "C" void kernel_launch(void* const* d_in, const int* in_sizes, int n_in,
                              void* d_out, int out_size) {
    const float* a = (const float*)d_in[0];
    const float* b = (const float*)d_in[1];
    int c = (int)(sqrt((double)out_size) + 0.5);   // out is c x c

    // Kernel A: c warp-pairs (each writes g(+d) and g(-d)), 16 warps/block
    {
        int blocks = (c + 15) / 16;
        compute_g_kernel<<<blocks, 512>>>(a, b, c);
    }

    // Kernel B: persistent work-stealing fill
    fill_kernel<<<FILL_GRID, 256>>>((float4*)d_out, c);
}

// round 9
// speedup vs baseline: 1.0245x; 1.0245x over previous
#include <cuda_runtime.h>
#include <math.h>

// out[m,n] = rope(a,m) . rope(b,n) depends only on (m-n):
//   out[m,n] = sum_j P_j*cos((m-n)*f_j) + Q_j*sin((m-n)*f_j)
// Build g(d) once (2c-1 values), then Toeplitz broadcast-fill.

__device__ float g_table[32768];

// ---------------- Kernel A: generator table ----------------
// One warp produces BOTH g(+d) and g(-d) from one sincos pass:
//   g(+d) = sum P*cos + Q*sin ,  g(-d) = sum P*cos - Q*sin
__global__ void __launch_bounds__(1024) compute_g_kernel(
        const float* __restrict__ a,
        const float* __restrict__ b,
        int c) {
    __shared__ float  Psh[64];
    __shared__ float  Qsh[64];
    __shared__ double Fsh[64];

    const int t = threadIdx.x;
    if (t < 64) {
        float a1 = a[t], a2 = a[t + 64];
        float b1 = b[t], b2 = b[t + 64];
        Psh[t] = a1 * b1 + a2 * b2;
        Qsh[t] = a1 * b2 - a2 * b1;
        // inv_freq[j] = 10000^(-j/64) = exp(-j * ln(10000)/64)
        Fsh[t] = exp(-(double)t * 0.14391156831212785);
    }
    __syncthreads();

    const int lane = t & 31;
    const int i    = blockIdx.x * (blockDim.x >> 5) + (t >> 5);  // d = i
    if (i >= c) return;

    const double d      = (double)i;
    const double inv2pi = 0.15915494309189535;
    const double twopi  = 6.283185307179586;

    float accP = 0.0f, accQ = 0.0f;
#pragma unroll
    for (int jj = 0; jj < 2; jj++) {
        int j = lane + jj * 32;
        double ang = d * Fsh[j];
        double k   = rint(ang * inv2pi);       // double range reduction
        float  r   = (float)(ang - k * twopi); // safe for fast-math sincosf
        float s, co;
        sincosf(r, &s, &co);
        accP += Psh[j] * co;
        accQ += Qsh[j] * s;
    }
#pragma unroll
    for (int o = 16; o; o >>= 1) {
        accP += __shfl_xor_sync(0xFFFFFFFFu, accP, o);
        accQ += __shfl_xor_sync(0xFFFFFFFFu, accQ, o);
    }

    if (lane == 0) {
        g_table[(c - 1) + i] = accP + accQ;   // g(+d)
        g_table[(c - 1) - i] = accP - accQ;   // g(-d)
    }
}

// ---------------- Kernel B: Toeplitz fill via smem staging ----------------
// Tile: 32 x 1024 per block (256 threads, one float4-column per thread).
// Reversed slice rsm0[k] = g[hi-k] stored in 4 shift-copies so every
// (row, col4) access is an aligned, conflict-free LDS.128.
// Exact R5 configuration (best measured: 43.0us) + streaming stores.
#define TROWS   32
#define TCOLS   1024
#define KLEN    (TCOLS + TROWS - 1)     // 1055 used indices
#define SSTRIDE 1060                    // float stride per copy (16B-mult)

__global__ void __launch_bounds__(256) fill_kernel(float4* __restrict__ out, int c) {
    __shared__ float rsm[4 * SSTRIDE];

    const int t  = threadIdx.x;
    const int m0 = blockIdx.y * TROWS;
    const int n0 = blockIdx.x * TCOLS;

    // base0 = g-index of out[m0][n0]; hi = max g-index this tile touches
    const int base0 = (c - 1) + m0 - n0;
    const int hi    = base0 + TROWS - 1;
    const int gmax  = 2 * c - 2;

    // Fill 4 shifted reversed copies: copy_s[k] = g[hi - k - s]
#pragma unroll
    for (int s = 0; s < 4; s++) {
        for (int k = t; k < KLEN; k += 256) {
            int gi = hi - k - s;
            float v = (gi >= 0 && gi <= gmax) ? g_table[gi] : 0.0f;
            rsm[s * SSTRIDE + k] = v;
        }
    }
    __syncthreads();

    const int cq = c >> 2;
    float4* orow = out + (size_t)m0 * (size_t)cq + (n0 >> 2) + t;

    // row r, column 4t+e  ->  g[base0 + r - 4t - e] = rsm0[x + 4t + e],
    // x = TROWS-1-r.  With s = x&3: aligned float4 at copy_s[(x-s) + 4t].
#pragma unroll
    for (int r = 0; r < TROWS; r++) {
        const int x = TROWS - 1 - r;
        const int s = x & 3;                      // compile-time per r
        const float4* src =
            (const float4*)(rsm + s * SSTRIDE + (x - s)) + t;
        __stcs(orow + (size_t)r * (size_t)cq, *src);   // streaming store
    }
}

extern "C" void kernel_launch(void* const* d_in, const int* in_sizes, int n_in,
                              void* d_out, int out_size) {
    const float* a = (const float*)d_in[0];
    const float* b = (const float*)d_in[1];
    int c = (int)(sqrt((double)out_size) + 0.5);   // out is c x c

    // Kernel A: c warp-pairs (each writes g(+d) and g(-d)), 32 warps/block
    {
        int blocks = (c + 31) / 32;
        compute_g_kernel<<<blocks, 1024>>>(a, b, c);
    }

    // Kernel B: tiled broadcast fill (2048 blocks for c=8192)
    {
        dim3 grid(c / TCOLS, c / TROWS);
        fill_kernel<<<grid, 256>>>((float4*)d_out, c);
    }
}

// round 10
// speedup vs baseline: 1.1397x; 1.1124x over previous
#include <cuda_runtime.h>
#include <math.h>

// out[m,n] = rope(a,m) . rope(b,n) depends only on (m-n):
//   out[m,n] = sum_j P_j*cos((m-n)*f_j) + Q_j*sin((m-n)*f_j)
// Build g(d) once (2c-1 values), then Toeplitz broadcast-fill.

#define GPAD 64                      // front pad: absorbs edge-tile underflow
__device__ float g_table[32768 + 2 * GPAD];

// ---------------- Kernel A: generator table, all-fp32 ----------------
// One warp produces BOTH g(+d) and g(-d) from one sincos pass:
//   g(+d) = sum P*cos + Q*sin ,  g(-d) = sum P*cos - Q*sin
// Range reduction: exact fp32 via FMA-Dekker product split + Cody-Waite
// (c1 = 6.28125 has 9 mantissa bits -> k*c1 exact for k < 2^15).
__global__ void __launch_bounds__(1024) compute_g_kernel(
        const float* __restrict__ a,
        const float* __restrict__ b,
        int c) {
    __shared__ float  Psh[64];
    __shared__ float  Qsh[64];
    __shared__ float2 Fsh[64];       // (f_hi, f_lo) split of inv_freq

    const int t = threadIdx.x;
    if (t < 64) {
        float a1 = a[t], a2 = a[t + 64];
        float b1 = b[t], b2 = b[t + 64];
        Psh[t] = a1 * b1 + a2 * b2;
        Qsh[t] = a1 * b2 - a2 * b1;
        // inv_freq[j] = 10000^(-j/64) = exp(-j * ln(10000)/64)
        double f  = exp(-(double)t * 0.14391156831212785);
        float  fh = (float)f;
        Fsh[t] = make_float2(fh, (float)(f - (double)fh));
    }
    __syncthreads();

    const int lane = t & 31;
    const int i    = blockIdx.x * (blockDim.x >> 5) + (t >> 5);  // d = i
    if (i >= c) return;

    const float d       = (float)i;              // exact (i < 2^24)
    const float inv2pi  = 0.15915494309189535f;
    const float c1      = 6.28125f;              // 2pi split, k*c1 exact
    const float c2      = 1.9353071795864769e-3f;

    float accP = 0.0f, accQ = 0.0f;
#pragma unroll
    for (int jj = 0; jj < 2; jj++) {
        int j = lane + jj * 32;
        float2 f = Fsh[j];
        float p1 = d * f.x;
        float p2 = fmaf(d, f.x, -p1);            // exact residual (Dekker)
        float k  = rintf(p1 * inv2pi);
        float r  = fmaf(-k, c1, p1);             // exact
        r        = fmaf(-k, c2, r);
        r       += fmaf(d, f.y, p2);             // low-order corrections
        float s, co;
        sincosf(r, &s, &co);
        accP += Psh[j] * co;
        accQ += Qsh[j] * s;
    }
#pragma unroll
    for (int o = 16; o; o >>= 1) {
        accP += __shfl_xor_sync(0xFFFFFFFFu, accP, o);
        accQ += __shfl_xor_sync(0xFFFFFFFFu, accQ, o);
    }

    if (lane == 0) {
        g_table[GPAD + (c - 1) + i] = accP + accQ;   // g(+d)
        g_table[GPAD + (c - 1) - i] = accP - accQ;   // g(-d)
    }
}

// ---------------- Kernel B: Toeplitz fill via smem staging ----------------
// Tile: 32 x 1024 per block (256 threads, one float4-column per thread).
// Reversed slice rsm0[k] = g[hi-k] stored in 4 shift-copies so every
// (row, col4) access is an aligned, conflict-free LDS.128.
// Exact R6 configuration (best measured fill: 43.0us), plain stores.
#define TROWS   32
#define TCOLS   1024
#define KLEN    (TCOLS + TROWS - 1)     // 1055 used indices
#define SSTRIDE 1060                    // float stride per copy (16B-mult)

__global__ void __launch_bounds__(256) fill_kernel(float4* __restrict__ out, int c) {
    __shared__ float rsm[4 * SSTRIDE];

    const int t  = threadIdx.x;
    const int m0 = blockIdx.y * TROWS;
    const int n0 = blockIdx.x * TCOLS;

    // base0 = g-index of out[m0][n0]; hi = max g-index this tile touches
    const int base0 = (c - 1) + m0 - n0;
    const int hi    = base0 + TROWS - 1;

    // Fill 4 shifted reversed copies: copy_s[k] = g[hi - k - s].
    // Index underflow at edge tiles (>= -34) is absorbed by GPAD; those
    // lanes stage garbage-free zeros that no in-range output ever reads.
#pragma unroll
    for (int s = 0; s < 4; s++) {
        for (int k = t; k < KLEN; k += 256) {
            rsm[s * SSTRIDE + k] = g_table[GPAD + hi - k - s];
        }
    }
    __syncthreads();

    const int cq = c >> 2;
    float4* orow = out + (size_t)m0 * (size_t)cq + (n0 >> 2) + t;

    // row r, column 4t+e  ->  g[base0 + r - 4t - e] = rsm0[x + 4t + e],
    // x = TROWS-1-r.  With s = x&3: aligned float4 at copy_s[(x-s) + 4t].
#pragma unroll
    for (int r = 0; r < TROWS; r++) {
        const int x = TROWS - 1 - r;
        const int s = x & 3;                      // compile-time per r
        const float4* src =
            (const float4*)(rsm + s * SSTRIDE + (x - s)) + t;
        orow[(size_t)r * (size_t)cq] = *src;
    }
}

extern "C" void kernel_launch(void* const* d_in, const int* in_sizes, int n_in,
                              void* d_out, int out_size) {
    const float* a = (const float*)d_in[0];
    const float* b = (const float*)d_in[1];
    int c = (int)(sqrt((double)out_size) + 0.5);   // out is c x c

    // Kernel A: c warp-pairs (each writes g(+d) and g(-d)), 32 warps/block
    {
        int blocks = (c + 31) / 32;
        compute_g_kernel<<<blocks, 1024>>>(a, b, c);
    }

    // Kernel B: tiled broadcast fill (2048 blocks for c=8192)
    {
        dim3 grid(c / TCOLS, c / TROWS);
        fill_kernel<<<grid, 256>>>((float4*)d_out, c);
    }
}

// round 11
// speedup vs baseline: 1.2317x; 1.0808x over previous
#include <cuda_runtime.h>
#include <math.h>

// out[m,n] = rope(a,m) . rope(b,n) depends only on (m-n):
//   out[m,n] = sum_j P_j*cos((m-n)*f_j) + Q_j*sin((m-n)*f_j)
// Build g(d) once (2c-1 values), then Toeplitz broadcast-fill.

#define GPAD 64                      // front pad: absorbs edge-tile underflow
__device__ float g_table[32768 + 2 * GPAD];

// ---------------- Kernel A: generator table, all-fp32 ----------------
// One warp produces BOTH g(+d) and g(-d) from one sincos pass:
//   g(+d) = sum P*cos + Q*sin ,  g(-d) = sum P*cos - Q*sin
// Range reduction: exact fp32 via FMA-Dekker product split + Cody-Waite
// (c1 = 6.28125 has 9 mantissa bits -> k*c1 exact for k < 2^15).
__global__ void __launch_bounds__(1024) compute_g_kernel(
        const float* __restrict__ a,
        const float* __restrict__ b,
        int c) {
    __shared__ float  Psh[64];
    __shared__ float  Qsh[64];
    __shared__ float2 Fsh[64];       // (f_hi, f_lo) split of inv_freq

    const int t = threadIdx.x;
    if (t < 64) {
        float a1 = a[t], a2 = a[t + 64];
        float b1 = b[t], b2 = b[t + 64];
        Psh[t] = a1 * b1 + a2 * b2;
        Qsh[t] = a1 * b2 - a2 * b1;
        // inv_freq[j] = 10000^(-j/64) = exp(-j * ln(10000)/64)
        double f  = exp(-(double)t * 0.14391156831212785);
        float  fh = (float)f;
        Fsh[t] = make_float2(fh, (float)(f - (double)fh));
    }
    __syncthreads();

    const int lane = t & 31;
    const int i    = blockIdx.x * (blockDim.x >> 5) + (t >> 5);  // d = i
    if (i >= c) return;

    const float d       = (float)i;              // exact (i < 2^24)
    const float inv2pi  = 0.15915494309189535f;
    const float c1      = 6.28125f;              // 2pi split, k*c1 exact
    const float c2      = 1.9353071795864769e-3f;

    float accP = 0.0f, accQ = 0.0f;
#pragma unroll
    for (int jj = 0; jj < 2; jj++) {
        int j = lane + jj * 32;
        float2 f = Fsh[j];
        float p1 = d * f.x;
        float p2 = fmaf(d, f.x, -p1);            // exact residual (Dekker)
        float k  = rintf(p1 * inv2pi);
        float r  = fmaf(-k, c1, p1);             // exact
        r        = fmaf(-k, c2, r);
        r       += fmaf(d, f.y, p2);             // low-order corrections
        float s, co;
        sincosf(r, &s, &co);
        accP += Psh[j] * co;
        accQ += Qsh[j] * s;
    }
#pragma unroll
    for (int o = 16; o; o >>= 1) {
        accP += __shfl_xor_sync(0xFFFFFFFFu, accP, o);
        accQ += __shfl_xor_sync(0xFFFFFFFFu, accQ, o);
    }

    if (lane == 0) {
        g_table[GPAD + (c - 1) + i] = accP + accQ;   // g(+d)
        g_table[GPAD + (c - 1) - i] = accP - accQ;   // g(-d)
    }
}

// ---------------- Kernel B: register-window Toeplitz fill ----------------
// Tile: 32 x 1024 per block (256 threads, one float4-column per thread).
// Stage ONE reversed slice rsm[k] = g[hi - k] (k = 0..1055). Thread t's
// entire 32-row output reads only rsm[4t .. 4t+35]: load it once as 9
// aligned LDS.128 into registers, then emit 32 float4 rows with fully
// static window indices. L1 work per 512B stored drops from 8 to ~5 cyc.
#define TROWS   32
#define TCOLS   1024
#define KLEN    1056                   // window coverage: 4*255 + 36
#define SSTRIDE 1060

__global__ void __launch_bounds__(256, 5) fill_kernel(float4* __restrict__ out, int c) {
    __shared__ float rsm[SSTRIDE];

    const int t  = threadIdx.x;
    const int m0 = blockIdx.y * TROWS;
    const int n0 = blockIdx.x * TCOLS;

    // base0 = g-index of out[m0][n0]; hi = max g-index this tile touches
    const int base0 = (c - 1) + m0 - n0;
    const int hi    = base0 + TROWS - 1;

    // Stage reversed slice: rsm[k] = g[hi - k]. Edge-tile underflow
    // (gi >= -1) is absorbed by GPAD.
    for (int k = t; k < KLEN; k += 256)
        rsm[k] = g_table[GPAD + hi - k];
    __syncthreads();

    // Load the 36-float per-thread window as 9 aligned float4s.
    float w[36];
#pragma unroll
    for (int q = 0; q < 9; q++) {
        float4 v = ((const float4*)rsm)[t + q];
        w[4 * q + 0] = v.x;
        w[4 * q + 1] = v.y;
        w[4 * q + 2] = v.z;
        w[4 * q + 3] = v.w;
    }

    const int cq = c >> 2;
    float4* orow = out + (size_t)m0 * (size_t)cq + (n0 >> 2) + t;

    // row r, col 4t+e -> g[base0 + r - 4t - e] = rsm[(31-r) + 4t + e]
    //                  = w[(31-r) + e]   (static indices after unroll)
#pragma unroll
    for (int r = 0; r < TROWS; r++) {
        const int x = TROWS - 1 - r;
        float4 o;
        o.x = w[x + 0];
        o.y = w[x + 1];
        o.z = w[x + 2];
        o.w = w[x + 3];
        orow[(size_t)r * (size_t)cq] = o;
    }
}

extern "C" void kernel_launch(void* const* d_in, const int* in_sizes, int n_in,
                              void* d_out, int out_size) {
    const float* a = (const float*)d_in[0];
    const float* b = (const float*)d_in[1];
    int c = (int)(sqrt((double)out_size) + 0.5);   // out is c x c

    // Kernel A: c warp-pairs (each writes g(+d) and g(-d)), 32 warps/block
    {
        int blocks = (c + 31) / 32;
        compute_g_kernel<<<blocks, 1024>>>(a, b, c);
    }

    // Kernel B: register-window broadcast fill (2048 blocks for c=8192)
    {
        dim3 grid(c / TCOLS, c / TROWS);
        fill_kernel<<<grid, 256>>>((float4*)d_out, c);
    }
}